// round 15
// baseline (speedup 1.0000x reference)
#include <cuda_runtime.h>
#include <math.h>

#define T_STEPS 500
#define BATCH   128
#define FDIM    128
#define HDIM    512
#define ODIM    32

#define NG  16     // batch groups
#define GSZ 8      // batches per group
#define NS  8      // H slices (CTAs per group)
#define DSTW 64    // dst neurons per slice

#define GBM 128
#define GBN 128
#define GBK 32

// Device-global scratch (sanctioned allocation-free path)
__device__ float g_iin[T_STEPS * BATCH * HDIM];          // x @ W_in^T
__device__ float g_wrecT[HDIM * HDIM];                   // W_rec^T [src][dst]
__device__ float g_woutT[HDIM * ODIM];                   // W_out^T [h][o]
__device__ unsigned long long g_zall[T_STEPS * NG * GSZ * NS];  // spike masks
__device__ int   g_sync[T_STEPS * NG];                   // per-(t,group) barrier

// ---------------------------------------------------------------------------
// Transposes + zero per-replay sync counters
// ---------------------------------------------------------------------------
__global__ void transpose_kernel(const float* __restrict__ W_rec,
                                 const float* __restrict__ W_out) {
    int idx = blockIdx.x * blockDim.x + threadIdx.x;
    if (idx < HDIM * HDIM) {
        int r = idx / HDIM, c = idx % HDIM;
        g_wrecT[c * HDIM + r] = W_rec[idx];
    }
    if (idx < ODIM * HDIM) {
        int o = idx / HDIM, h = idx % HDIM;
        g_woutT[h * ODIM + o] = W_out[idx];
    }
    if (idx < T_STEPS * NG) g_sync[idx] = 0;
}

// ---------------------------------------------------------------------------
// GEMM: g_iin[m,n] = sum_k X[m,k] * W_in[n,k]   (R2 version — proven fastest)
// ---------------------------------------------------------------------------
__global__ void __launch_bounds__(256) gemm_iin_kernel(
    const float* __restrict__ X, const float* __restrict__ Win) {
    __shared__ float As[GBK][GBM + 4];
    __shared__ float Bs[GBK][GBN + 4];

    const int tid = threadIdx.x;
    const int bm = blockIdx.y;
    const int bn = blockIdx.x;
    const float* Xb = X   + (size_t)bm * GBM * FDIM;
    const float* Wb = Win + (size_t)bn * GBN * FDIM;

    const int ty = tid >> 4;
    const int tx = tid & 15;
    const int lrow = tid >> 3;
    const int lcol = (tid & 7) * 4;

    float acc[8][8] = {};

    for (int k0 = 0; k0 < FDIM; k0 += GBK) {
        #pragma unroll
        for (int p = 0; p < 4; p++) {
            int r = lrow + p * 32;
            float4 va = *(const float4*)(Xb + (size_t)r * FDIM + k0 + lcol);
            As[lcol + 0][r] = va.x; As[lcol + 1][r] = va.y;
            As[lcol + 2][r] = va.z; As[lcol + 3][r] = va.w;
            float4 vb = *(const float4*)(Wb + (size_t)r * FDIM + k0 + lcol);
            Bs[lcol + 0][r] = vb.x; Bs[lcol + 1][r] = vb.y;
            Bs[lcol + 2][r] = vb.z; Bs[lcol + 3][r] = vb.w;
        }
        __syncthreads();

        #pragma unroll
        for (int k = 0; k < GBK; k++) {
            float af[8], bf[8];
            *(float4*)(af)     = *(const float4*)&As[k][ty * 8];
            *(float4*)(af + 4) = *(const float4*)&As[k][ty * 8 + 4];
            *(float4*)(bf)     = *(const float4*)&Bs[k][tx * 8];
            *(float4*)(bf + 4) = *(const float4*)&Bs[k][tx * 8 + 4];
            #pragma unroll
            for (int i = 0; i < 8; i++)
                #pragma unroll
                for (int j = 0; j < 8; j++)
                    acc[i][j] += af[i] * bf[j];
        }
        __syncthreads();
    }

    float* C = g_iin + (size_t)(bm * GBM) * HDIM + bn * GBN;
    #pragma unroll
    for (int i = 0; i < 8; i++) {
        float4 v0, v1;
        v0.x = acc[i][0]; v0.y = acc[i][1]; v0.z = acc[i][2]; v0.w = acc[i][3];
        v1.x = acc[i][4]; v1.y = acc[i][5]; v1.z = acc[i][6]; v1.w = acc[i][7];
        float* Crow = C + (size_t)(ty * 8 + i) * HDIM + tx * 8;
        *(float4*)(Crow)     = v0;
        *(float4*)(Crow + 4) = v1;
    }
}

// ---------------------------------------------------------------------------
// SNN kernel — R13 semantics with 3 block barriers/step:
//  (B) replaced by __syncwarp (publishers + poller all in warp 0),
//  fetch+expand merged via 8-wide shuffle prefix scan (no s_mask staging).
// Offset lists byte-identical to R13 -> gather order/rounding unchanged.
// SMEM layout (bytes):
//   w_s     [512*64 f]  @0       131072
//   s_list  [8][512 i]  @131072   16384
//   s_half  [16 u32]    @147456      64
//   s_n     [8 i]       @147520      32   -> total 147552 (pad 147584)
// ---------------------------------------------------------------------------
#define SNN_SMEM 147584

__global__ void __launch_bounds__(512, 1) snn_kernel() {
    extern __shared__ char sh[];
    float*    w_s    = (float*)sh;
    int*      s_list = (int*)(sh + 131072);
    unsigned* s_half = (unsigned*)(sh + 147456);
    int*      s_n    = (int*)(sh + 147520);

    const int g    = blockIdx.x >> 3;
    const int s    = blockIdx.x & 7;
    const int tid  = threadIdx.x;
    const int warp = tid >> 5;
    const int lane = tid & 31;
    const int b    = warp >> 1;                 // local batch 0..7
    const int d    = ((warp & 1) << 5) + lane;  // dst 0..63

    // stage W_recT slice: w_s[h][d] = g_wrecT[h][s*64+d]
    for (int idx = tid; idx < HDIM * DSTW; idx += 512)
        w_s[idx] = g_wrecT[((idx >> 6) << 9) + (s << 6) + (idx & 63)];
    if (tid < 8) s_n[tid] = 0;
    __syncthreads();

    const int gb = (g << 3) + b;                // global batch
    float v = 0.f, ii = 0.f, aa = 0.f;
    const float* iin = g_iin + (size_t)gb * HDIM + (s << 6) + d;
    const char*  wp  = (const char*)w_s + ((size_t)d << 2);
    const int*   lp  = s_list + (b << 9);

    for (int t = 0; t < T_STEPS; t++) {
        float ic = __ldg(iin + (size_t)t * (BATCH * HDIM));

        // ---- SMEM gather over the precomputed offset list of batch b ----
        // (order frozen: position-mod-4 chains over the ascending-h list)
        const int nb = s_n[b];
        float a0 = 0.f, a1 = 0.f, a2 = 0.f, a3 = 0.f;
        int j = 0;
        for (; j + 4 <= nb; j += 4) {
            int4 o = *(const int4*)(lp + j);
            a0 += *(const float*)(wp + o.x);
            a1 += *(const float*)(wp + o.y);
            a2 += *(const float*)(wp + o.z);
            a3 += *(const float*)(wp + o.w);
        }
        for (; j < nb; j++)
            a0 += *(const float*)(wp + lp[j]);
        float rec = ((a0 + a1) + (a2 + a3));

        // ---- LIF-AdEx update (grouping mirrors the JAX reference) ----
        float dv   = 0.1f * ((((0.f - v) + 0.5f * expf((v - 1.f) * 2.f)) + ii) - aa);
        float vdec = v + dv;
        float idec = ii - 0.2f * ii;
        float adec = aa + 0.002f * (4.f * v - aa);
        int   z    = (vdec - 1.f) > 0.f;
        v  = z ? 0.f : vdec;
        ii = (idec + ic) + rec;
        aa = adec + (z ? 0.02f : 0.f);

        // ---- pack local 64-dst spike bits ----
        unsigned bal = __ballot_sync(0xffffffffu, z);
        if (lane == 0) s_half[warp] = bal;
        __syncthreads();                         // (A) gather reads + s_half done

        // ---- publish masks + group barrier (all warp 0; R4 protocol) ----
        if (warp == 0) {
            if (lane < 8) {
                unsigned long long m64 =
                    (unsigned long long)s_half[lane << 1] |
                    ((unsigned long long)s_half[(lane << 1) + 1] << 32);
                g_zall[(((size_t)t * NG + g) * GSZ + lane) * NS + s] = m64;
                __threadfence();
            }
            __syncwarp();                        // STGs+fences hb-before atomic
            if (lane == 0) {
                atomicAdd(&g_sync[t * NG + g], 1);
                volatile int* p = &g_sync[t * NG + g];
                while (*p < NS) __nanosleep(40);
                __threadfence();
            }
        }
        __syncthreads();                         // (B) all 8 CTAs published

        // ---- fetch + expand in one phase (shuffle prefix scan) ----
        if (tid < 64) {
            const int bb = tid >> 3, w8 = tid & 7;
            unsigned long long m = __ldcg(
                &g_zall[(((size_t)t * NG + g) * GSZ + bb) * NS + w8]);
            int c = __popcll(m);
            int pre = c;                         // inclusive scan within 8-seg
            #pragma unroll
            for (int dlt = 1; dlt < 8; dlt <<= 1) {
                int vv = __shfl_up_sync(0xffffffffu, pre, dlt, 8);
                if ((lane & 7) >= dlt) pre += vv;
            }
            int base = pre - c;                  // exclusive prefix
            int* out_l = s_list + (bb << 9) + base;
            const int off0 = w8 << 14;           // (w8*64) rows * 256 B
            while (m) {
                int bit = __ffsll(m) - 1;
                m &= m - 1;
                *out_l++ = off0 + (bit << 8);    // row h -> h*256 bytes
            }
            if (w8 == 7) s_n[bb] = pre;          // total count for batch bb
        }
        __syncthreads();                         // (C) lists ready for next step
    }
}

// ---------------------------------------------------------------------------
// Readout: one CTA per batch, 1024 threads (32 t-strided warps).
// W_outT staged in SMEM; 4-chain mask scan; warp 0 runs the IIR.
// ---------------------------------------------------------------------------
#define RDO_SMEM (65536 + T_STEPS * ODIM * 4)

__global__ void __launch_bounds__(1024) readout_kernel(
    const float* __restrict__ b_out, float* __restrict__ out) {
    extern __shared__ char rsh[];
    float* w_s   = (float*)rsh;                  // [512][32]
    float* y_buf = (float*)(rsh + 65536);        // [500][32]
    const int B    = blockIdx.x;
    const int tid  = threadIdx.x;
    const int warp = tid >> 5;
    const int lane = tid & 31;
    const int g    = B >> 3;
    const int bb   = B & 7;

    for (int idx = tid; idx < HDIM * ODIM; idx += 1024)
        w_s[idx] = g_woutT[idx];
    __syncthreads();

    float bo = b_out[lane];

    for (int t = warp; t < T_STEPS; t += 32) {
        const unsigned long long* mp =
            g_zall + (((size_t)t * NG + g) * GSZ + bb) * NS;
        float y0 = 0.f, y1 = 0.f, y2 = 0.f, y3 = 0.f;
        #pragma unroll
        for (int w8 = 0; w8 < 8; w8++) {
            unsigned long long m = __ldg(mp + w8);
            const float* wop = w_s + (w8 << 11) + lane;
            while (m) {
                int b0 = __ffsll(m) - 1; m &= m - 1;
                int b1 = -1, b2 = -1, b3 = -1;
                if (m) { b1 = __ffsll(m) - 1; m &= m - 1; }
                if (m) { b2 = __ffsll(m) - 1; m &= m - 1; }
                if (m) { b3 = __ffsll(m) - 1; m &= m - 1; }
                y0 += wop[b0 << 5];
                if (b1 >= 0) y1 += wop[b1 << 5];
                if (b2 >= 0) y2 += wop[b2 << 5];
                if (b3 >= 0) y3 += wop[b3 << 5];
            }
        }
        y_buf[t * ODIM + lane] = ((y0 + y1) + (y2 + y3)) + bo;
    }
    __syncthreads();

    if (warp == 0) {
        float o = y_buf[lane];                   // o0 = y[0]
        out[(size_t)B * ODIM + lane] = o;
        for (int t = 1; t < T_STEPS; t++) {
            float y = y_buf[t * ODIM + lane];
            o = o + 0.2231435511314f * (y - o);
            out[((size_t)t * BATCH + B) * ODIM + lane] = o;
        }
    }
}

// ---------------------------------------------------------------------------
extern "C" void kernel_launch(void* const* d_in, const int* in_sizes, int n_in,
                              void* d_out, int out_size) {
    const float* x     = (const float*)d_in[0];  // (T,B,F)
    const float* W_in  = (const float*)d_in[1];  // (H,F)
    const float* W_rec = (const float*)d_in[2];  // (H,H)
    const float* W_out = (const float*)d_in[3];  // (O,H)
    const float* b_out = (const float*)d_in[4];  // (O,)
    float* out = (float*)d_out;                  // (T,B,O)

    cudaFuncSetAttribute(snn_kernel,
                         cudaFuncAttributeMaxDynamicSharedMemorySize, SNN_SMEM);
    cudaFuncSetAttribute(readout_kernel,
                         cudaFuncAttributeMaxDynamicSharedMemorySize, RDO_SMEM);

    transpose_kernel<<<(HDIM * HDIM + 255) / 256, 256>>>(W_rec, W_out);

    dim3 ggrid(HDIM / GBN, (T_STEPS * BATCH) / GBM);  // (4, 500)
    gemm_iin_kernel<<<ggrid, 256>>>(x, W_in);

    snn_kernel<<<NG * NS, 512, SNN_SMEM>>>();

    readout_kernel<<<BATCH, 1024, RDO_SMEM>>>(b_out, out);
}

// round 16
// speedup vs baseline: 1.0821x; 1.0821x over previous
#include <cuda_runtime.h>
#include <math.h>

#define T_STEPS 500
#define BATCH   128
#define FDIM    128
#define HDIM    512
#define ODIM    32

#define NG  16     // batch groups
#define GSZ 8      // batches per group
#define NS  8      // H slices (CTAs per group)
#define DSTW 64    // dst neurons per slice

#define GBM 128
#define GBN 128
#define GBK 32

// Device-global scratch (sanctioned allocation-free path)
__device__ float g_iin[T_STEPS * BATCH * HDIM];          // x @ W_in^T
__device__ float g_wrecT[HDIM * HDIM];                   // W_rec^T [src][dst]
__device__ float g_woutT[HDIM * ODIM];                   // W_out^T [h][o]
__device__ unsigned long long g_zall[T_STEPS * NG * GSZ * NS];  // spike masks
__device__ int   g_sync[T_STEPS * NG];                   // per-(t,group) barrier

// ---------------------------------------------------------------------------
// Transposes + zero per-replay sync counters
// ---------------------------------------------------------------------------
__global__ void transpose_kernel(const float* __restrict__ W_rec,
                                 const float* __restrict__ W_out) {
    int idx = blockIdx.x * blockDim.x + threadIdx.x;
    if (idx < HDIM * HDIM) {
        int r = idx / HDIM, c = idx % HDIM;
        g_wrecT[c * HDIM + r] = W_rec[idx];
    }
    if (idx < ODIM * HDIM) {
        int o = idx / HDIM, h = idx % HDIM;
        g_woutT[h * ODIM + o] = W_out[idx];
    }
    if (idx < T_STEPS * NG) g_sync[idx] = 0;
}

// ---------------------------------------------------------------------------
// GEMM: g_iin[m,n] = sum_k X[m,k] * W_in[n,k]   (R2 version — proven fastest)
// ---------------------------------------------------------------------------
__global__ void __launch_bounds__(256) gemm_iin_kernel(
    const float* __restrict__ X, const float* __restrict__ Win) {
    __shared__ float As[GBK][GBM + 4];
    __shared__ float Bs[GBK][GBN + 4];

    const int tid = threadIdx.x;
    const int bm = blockIdx.y;
    const int bn = blockIdx.x;
    const float* Xb = X   + (size_t)bm * GBM * FDIM;
    const float* Wb = Win + (size_t)bn * GBN * FDIM;

    const int ty = tid >> 4;
    const int tx = tid & 15;
    const int lrow = tid >> 3;
    const int lcol = (tid & 7) * 4;

    float acc[8][8] = {};

    for (int k0 = 0; k0 < FDIM; k0 += GBK) {
        #pragma unroll
        for (int p = 0; p < 4; p++) {
            int r = lrow + p * 32;
            float4 va = *(const float4*)(Xb + (size_t)r * FDIM + k0 + lcol);
            As[lcol + 0][r] = va.x; As[lcol + 1][r] = va.y;
            As[lcol + 2][r] = va.z; As[lcol + 3][r] = va.w;
            float4 vb = *(const float4*)(Wb + (size_t)r * FDIM + k0 + lcol);
            Bs[lcol + 0][r] = vb.x; Bs[lcol + 1][r] = vb.y;
            Bs[lcol + 2][r] = vb.z; Bs[lcol + 3][r] = vb.w;
        }
        __syncthreads();

        #pragma unroll
        for (int k = 0; k < GBK; k++) {
            float af[8], bf[8];
            *(float4*)(af)     = *(const float4*)&As[k][ty * 8];
            *(float4*)(af + 4) = *(const float4*)&As[k][ty * 8 + 4];
            *(float4*)(bf)     = *(const float4*)&Bs[k][tx * 8];
            *(float4*)(bf + 4) = *(const float4*)&Bs[k][tx * 8 + 4];
            #pragma unroll
            for (int i = 0; i < 8; i++)
                #pragma unroll
                for (int j = 0; j < 8; j++)
                    acc[i][j] += af[i] * bf[j];
        }
        __syncthreads();
    }

    float* C = g_iin + (size_t)(bm * GBM) * HDIM + bn * GBN;
    #pragma unroll
    for (int i = 0; i < 8; i++) {
        float4 v0, v1;
        v0.x = acc[i][0]; v0.y = acc[i][1]; v0.z = acc[i][2]; v0.w = acc[i][3];
        v1.x = acc[i][4]; v1.y = acc[i][5]; v1.z = acc[i][6]; v1.w = acc[i][7];
        float* Crow = C + (size_t)(ty * 8 + i) * HDIM + tx * 8;
        *(float4*)(Crow)     = v0;
        *(float4*)(Crow + 4) = v1;
    }
}

// ---------------------------------------------------------------------------
// SNN kernel — R13 VERBATIM (best measured: 1558 total). CTA = (group g,
// slice s); R4 exchange protocol; popcount merged into expand (lists
// byte-identical to R4). Gather summation order == frozen spec.
// SMEM layout (bytes):
//   w_s     [512*64 f]  @0       131072
//   s_list  [8][512 i]  @131072   16384
//   s_mask  [64 u64]    @147456     512
//   s_half  [16 u32]    @147968      64
//   s_n     [8 i]       @148032      32   -> total 148064 (pad 148096)
// ---------------------------------------------------------------------------
#define SNN_SMEM 148096

__global__ void __launch_bounds__(512, 1) snn_kernel() {
    extern __shared__ char sh[];
    float*              w_s    = (float*)sh;
    int*                s_list = (int*)(sh + 131072);
    unsigned long long* s_mask = (unsigned long long*)(sh + 147456);
    unsigned*           s_half = (unsigned*)(sh + 147968);
    int*                s_n    = (int*)(sh + 148032);

    const int g    = blockIdx.x >> 3;
    const int s    = blockIdx.x & 7;
    const int tid  = threadIdx.x;
    const int warp = tid >> 5;
    const int lane = tid & 31;
    const int b    = warp >> 1;                 // local batch 0..7
    const int d    = ((warp & 1) << 5) + lane;  // dst 0..63

    // stage W_recT slice: w_s[h][d] = g_wrecT[h][s*64+d]
    for (int idx = tid; idx < HDIM * DSTW; idx += 512)
        w_s[idx] = g_wrecT[((idx >> 6) << 9) + (s << 6) + (idx & 63)];
    if (tid < 8) s_n[tid] = 0;
    __syncthreads();

    const int gb = (g << 3) + b;                // global batch
    float v = 0.f, ii = 0.f, aa = 0.f;
    const float* iin = g_iin + (size_t)gb * HDIM + (s << 6) + d;
    const char*  wp  = (const char*)w_s + ((size_t)d << 2);
    const int*   lp  = s_list + (b << 9);

    for (int t = 0; t < T_STEPS; t++) {
        float ic = __ldg(iin + (size_t)t * (BATCH * HDIM));

        // ---- SMEM gather over the precomputed offset list of batch b ----
        // (order frozen: position-mod-4 chains over the ascending-h list)
        const int nb = s_n[b];
        float a0 = 0.f, a1 = 0.f, a2 = 0.f, a3 = 0.f;
        int j = 0;
        for (; j + 4 <= nb; j += 4) {
            int4 o = *(const int4*)(lp + j);
            a0 += *(const float*)(wp + o.x);
            a1 += *(const float*)(wp + o.y);
            a2 += *(const float*)(wp + o.z);
            a3 += *(const float*)(wp + o.w);
        }
        for (; j < nb; j++)
            a0 += *(const float*)(wp + lp[j]);
        float rec = ((a0 + a1) + (a2 + a3));

        // ---- LIF-AdEx update (grouping mirrors the JAX reference) ----
        float dv   = 0.1f * ((((0.f - v) + 0.5f * expf((v - 1.f) * 2.f)) + ii) - aa);
        float vdec = v + dv;
        float idec = ii - 0.2f * ii;
        float adec = aa + 0.002f * (4.f * v - aa);
        int   z    = (vdec - 1.f) > 0.f;
        v  = z ? 0.f : vdec;
        ii = (idec + ic) + rec;
        aa = adec + (z ? 0.02f : 0.f);

        // ---- pack local 64-dst spike bits ----
        unsigned bal = __ballot_sync(0xffffffffu, z);
        if (lane == 0) s_half[warp] = bal;
        __syncthreads();                         // (A) gather reads + s_half done

        // ---- publish masks (R4 protocol, verbatim) ----
        if (tid < 8) {
            unsigned long long m64 =
                (unsigned long long)s_half[tid << 1] |
                ((unsigned long long)s_half[(tid << 1) + 1] << 32);
            g_zall[(((size_t)t * NG + g) * GSZ + tid) * NS + s] = m64;
            __threadfence();
        }
        __syncthreads();                         // (B) publishes + fences done

        // ---- group barrier (8 slice-CTAs, all co-resident) ----
        if (tid == 0) {
            atomicAdd(&g_sync[t * NG + g], 1);
            volatile int* p = &g_sync[t * NG + g];
            while (*p < NS) __nanosleep(40);
        }
        __syncthreads();                         // barrier passed

        // ---- fetch merged masks ----
        if (tid < 64)
            s_mask[tid] = __ldcg(
                &g_zall[(((size_t)t * NG + g) * GSZ + (tid >> 3)) * NS + (tid & 7)]);
        __syncthreads();                         // (C) masks ready

        // ---- expand masks -> per-batch byte-offset lists ----
        // (prefix popcounts computed inline; lists byte-identical to R4)
        if (tid < 64) {
            const int bb = tid >> 3, w8 = tid & 7;
            const unsigned long long* mbase = s_mask + (bb << 3);
            int base = 0;
            #pragma unroll
            for (int q = 0; q < 7; q++)
                if (q < w8) base += __popcll(mbase[q]);
            unsigned long long m = mbase[w8];
            int* out_l = s_list + (bb << 9) + base;
            const int off0 = w8 << 14;            // (w8*64) rows * 256 B
            while (m) {
                int bit = __ffsll(m) - 1;
                m &= m - 1;
                *out_l++ = off0 + (bit << 8);     // row h -> h*256 bytes
            }
            if (w8 == 7) s_n[bb] = base + __popcll(mbase[7]);
        }
        __syncthreads();                         // (D) lists ready for next step
    }
}

// ---------------------------------------------------------------------------
// Readout — R14 version (measured 77 us): 1024 threads, W_outT in SMEM,
// 4-chain mask scan; warp 0 runs the serial IIR filter.
// ---------------------------------------------------------------------------
#define RDO_SMEM (65536 + T_STEPS * ODIM * 4)

__global__ void __launch_bounds__(1024) readout_kernel(
    const float* __restrict__ b_out, float* __restrict__ out) {
    extern __shared__ char rsh[];
    float* w_s   = (float*)rsh;                  // [512][32]
    float* y_buf = (float*)(rsh + 65536);        // [500][32]
    const int B    = blockIdx.x;
    const int tid  = threadIdx.x;
    const int warp = tid >> 5;
    const int lane = tid & 31;
    const int g    = B >> 3;
    const int bb   = B & 7;

    for (int idx = tid; idx < HDIM * ODIM; idx += 1024)
        w_s[idx] = g_woutT[idx];
    __syncthreads();

    float bo = b_out[lane];

    for (int t = warp; t < T_STEPS; t += 32) {
        const unsigned long long* mp =
            g_zall + (((size_t)t * NG + g) * GSZ + bb) * NS;
        float y0 = 0.f, y1 = 0.f, y2 = 0.f, y3 = 0.f;
        #pragma unroll
        for (int w8 = 0; w8 < 8; w8++) {
            unsigned long long m = __ldg(mp + w8);
            const float* wop = w_s + (w8 << 11) + lane;
            while (m) {
                int b0 = __ffsll(m) - 1; m &= m - 1;
                int b1 = -1, b2 = -1, b3 = -1;
                if (m) { b1 = __ffsll(m) - 1; m &= m - 1; }
                if (m) { b2 = __ffsll(m) - 1; m &= m - 1; }
                if (m) { b3 = __ffsll(m) - 1; m &= m - 1; }
                y0 += wop[b0 << 5];
                if (b1 >= 0) y1 += wop[b1 << 5];
                if (b2 >= 0) y2 += wop[b2 << 5];
                if (b3 >= 0) y3 += wop[b3 << 5];
            }
        }
        y_buf[t * ODIM + lane] = ((y0 + y1) + (y2 + y3)) + bo;
    }
    __syncthreads();

    if (warp == 0) {
        float o = y_buf[lane];                   // o0 = y[0]
        out[(size_t)B * ODIM + lane] = o;
        for (int t = 1; t < T_STEPS; t++) {
            float y = y_buf[t * ODIM + lane];
            o = o + 0.2231435511314f * (y - o);
            out[((size_t)t * BATCH + B) * ODIM + lane] = o;
        }
    }
}

// ---------------------------------------------------------------------------
extern "C" void kernel_launch(void* const* d_in, const int* in_sizes, int n_in,
                              void* d_out, int out_size) {
    const float* x     = (const float*)d_in[0];  // (T,B,F)
    const float* W_in  = (const float*)d_in[1];  // (H,F)
    const float* W_rec = (const float*)d_in[2];  // (H,H)
    const float* W_out = (const float*)d_in[3];  // (O,H)
    const float* b_out = (const float*)d_in[4];  // (O,)
    float* out = (float*)d_out;                  // (T,B,O)

    cudaFuncSetAttribute(snn_kernel,
                         cudaFuncAttributeMaxDynamicSharedMemorySize, SNN_SMEM);
    cudaFuncSetAttribute(readout_kernel,
                         cudaFuncAttributeMaxDynamicSharedMemorySize, RDO_SMEM);

    transpose_kernel<<<(HDIM * HDIM + 255) / 256, 256>>>(W_rec, W_out);

    dim3 ggrid(HDIM / GBN, (T_STEPS * BATCH) / GBM);  // (4, 500)
    gemm_iin_kernel<<<ggrid, 256>>>(x, W_in);

    snn_kernel<<<NG * NS, 512, SNN_SMEM>>>();

    readout_kernel<<<BATCH, 1024, RDO_SMEM>>>(b_out, out);
}